// round 1
// baseline (speedup 1.0000x reference)
#include <cuda_runtime.h>
#include <math.h>

// Problem constants (fixed by reference setup_inputs)
#define BROWS 8192
#define DIM   512
#define INV_T 14.285714285714286f   // 1 / 0.07

// GEMM tiling
#define TM 128
#define TN 128
#define KC 8
#define JSPLIT 4
#define JCHUNK (BROWS / JSPLIT)     // 2048
#define NTILES (JCHUNK / TN)        // 16
#define KCHUNKS (DIM / KC)          // 64

// Scratch (static device globals — no allocation)
__device__ float g_f[BROWS * DIM];           // normalized features (16 MB)
__device__ float g_partial[JSPLIT][BROWS];   // per-j-split row sums of exp
__device__ float g_rowval[BROWS];            // lse_i - picked_i

// ---------------------------------------------------------------------------
// Kernel A: row L2-normalize.  One warp per row, 8 rows per block.
// ---------------------------------------------------------------------------
__global__ void normalize_kernel(const float* __restrict__ x) {
    int row  = blockIdx.x * 8 + threadIdx.y;
    int lane = threadIdx.x;
    const float* xr = x + (size_t)row * DIM;
    float v[16];
    float s = 0.f;
#pragma unroll
    for (int i = 0; i < 16; i++) {
        v[i] = xr[lane + i * 32];
        s += v[i] * v[i];
    }
#pragma unroll
    for (int o = 16; o; o >>= 1) s += __shfl_xor_sync(0xffffffffu, s, o);
    float inv = 1.0f / fmaxf(sqrtf(s), 1e-12f);
    float* fr = g_f + (size_t)row * DIM;
#pragma unroll
    for (int i = 0; i < 16; i++) fr[lane + i * 32] = v[i] * inv;
}

// ---------------------------------------------------------------------------
// Kernel B: fused 128x128x512 fp32 GEMM tiles + exp row-sum accumulation.
// Block = 256 threads (16x16), each thread computes an 8x8 microtile split as
// rows {ty*4..+3, 64+ty*4..+3} x cols {tx*4..+3, 64+tx*4..+3}  (conflict-free
// LDS.128: 16 lanes * 16B stride covers all 32 banks exactly once).
// Grid = (BROWS/TM, JSPLIT); each block owns a disjoint (row-block, j-range),
// so g_partial is written with plain stores — fully deterministic.
// ---------------------------------------------------------------------------
__global__ __launch_bounds__(256, 2) void gemm_lse_kernel() {
    __shared__ float As[KC][TM + 4];
    __shared__ float Bs[KC][TN + 4];
    __shared__ float red[TM][17];

    const int tid = threadIdx.x;
    const int tx = tid & 15;
    const int ty = tid >> 4;
    const int r0 = blockIdx.x * TM;
    const int j0base = blockIdx.y * JCHUNK;

    // staging-load mapping: 2 threads per row, one float4 each
    const int lrow = tid >> 1;           // 0..127
    const int seg  = (tid & 1) * 4;      // 0 or 4 (floats)

    float rowsum[8];
#pragma unroll
    for (int i = 0; i < 8; i++) rowsum[i] = 0.f;

    for (int t = 0; t < NTILES; t++) {
        const int j0 = j0base + t * TN;
        float acc[8][8];
#pragma unroll
        for (int i = 0; i < 8; i++)
#pragma unroll
            for (int j = 0; j < 8; j++) acc[i][j] = 0.f;

        // prologue: stage k-chunk 0 in registers
        float4 ra = *(const float4*)&g_f[(size_t)(r0 + lrow) * DIM + seg];
        float4 rb = *(const float4*)&g_f[(size_t)(j0 + lrow) * DIM + seg];

        for (int c = 0; c < KCHUNKS; c++) {
            // commit staged chunk to smem (transposed: [k][row])
            As[seg + 0][lrow] = ra.x; As[seg + 1][lrow] = ra.y;
            As[seg + 2][lrow] = ra.z; As[seg + 3][lrow] = ra.w;
            Bs[seg + 0][lrow] = rb.x; Bs[seg + 1][lrow] = rb.y;
            Bs[seg + 2][lrow] = rb.z; Bs[seg + 3][lrow] = rb.w;
            __syncthreads();

            // prefetch next chunk (latency hidden under the 8 k-steps below)
            if (c + 1 < KCHUNKS) {
                const int kk = (c + 1) * KC;
                ra = *(const float4*)&g_f[(size_t)(r0 + lrow) * DIM + kk + seg];
                rb = *(const float4*)&g_f[(size_t)(j0 + lrow) * DIM + kk + seg];
            }

#pragma unroll
            for (int k = 0; k < KC; k++) {
                float a[8], b[8];
                float4 a0 = *(const float4*)&As[k][ty * 4];
                float4 a1 = *(const float4*)&As[k][64 + ty * 4];
                float4 b0 = *(const float4*)&Bs[k][tx * 4];
                float4 b1 = *(const float4*)&Bs[k][64 + tx * 4];
                a[0]=a0.x; a[1]=a0.y; a[2]=a0.z; a[3]=a0.w;
                a[4]=a1.x; a[5]=a1.y; a[6]=a1.z; a[7]=a1.w;
                b[0]=b0.x; b[1]=b0.y; b[2]=b0.z; b[3]=b0.w;
                b[4]=b1.x; b[5]=b1.y; b[6]=b1.z; b[7]=b1.w;
#pragma unroll
                for (int i = 0; i < 8; i++)
#pragma unroll
                    for (int j = 0; j < 8; j++)
                        acc[i][j] = fmaf(a[i], b[j], acc[i][j]);
            }
            __syncthreads();
        }

        // fold this j-tile into the per-row exp sums.
        // max over all j is the diagonal (dot = 1), so shift is the constant 1.
#pragma unroll
        for (int i = 0; i < 8; i++) {
            float s = rowsum[i];
#pragma unroll
            for (int j = 0; j < 8; j++)
                s += __expf((acc[i][j] - 1.0f) * INV_T);
            rowsum[i] = s;
        }
    }

    // reduce the 16 tx-threads that share each row (fixed order -> deterministic)
#pragma unroll
    for (int i = 0; i < 8; i++) {
        int lr = (i < 4) ? (ty * 4 + i) : (64 + ty * 4 + (i - 4));
        red[lr][tx] = rowsum[i];
    }
    __syncthreads();
    if (tid < TM) {
        float s = 0.f;
#pragma unroll
        for (int x = 0; x < 16; x++) s += red[tid][x];
        g_partial[blockIdx.y][r0 + tid] = s;
    }
}

// ---------------------------------------------------------------------------
// Kernel C: labels (column index 0/1), picked dot, lse, per-row value.
// One warp per row.
// ---------------------------------------------------------------------------
__global__ void pick_kernel(const int* __restrict__ ids,
                            const int* __restrict__ anchor) {
    int row  = blockIdx.x * 8 + threadIdx.y;
    int lane = threadIdx.x;

    int aid       = ids[anchor[0]];
    int same_i    = (ids[row] == aid);
    int same_last = (ids[BROWS - 1] == aid);
    int label;
    if (row == BROWS - 1)
        label = (same_last && (ids[BROWS - 2] == aid)) ? 1 : 0;
    else
        label = (same_i && same_last) ? 1 : 0;

    const float* fi = g_f + (size_t)row * DIM;
    const float* fc = g_f + (size_t)label * DIM;
    float d = 0.f;
#pragma unroll
    for (int i = 0; i < 16; i++)
        d = fmaf(fi[lane + i * 32], fc[lane + i * 32], d);
#pragma unroll
    for (int o = 16; o; o >>= 1) d += __shfl_xor_sync(0xffffffffu, d, o);

    if (lane == 0) {
        float rs = 0.f;
#pragma unroll
        for (int p = 0; p < JSPLIT; p++) rs += g_partial[p][row];
        float lse = INV_T + logf(rs);          // shift was exactly 1/T
        g_rowval[row] = lse - d * INV_T;       // -(picked logprob)
    }
}

// ---------------------------------------------------------------------------
// Kernel D: deterministic final reduction -> scalar loss
// ---------------------------------------------------------------------------
__global__ void finalize_kernel(float* __restrict__ out) {
    __shared__ float sm[256];
    int t = threadIdx.x;
    float s = 0.f;
    for (int i = t; i < BROWS; i += 256) s += g_rowval[i];
    sm[t] = s;
    __syncthreads();
#pragma unroll
    for (int o = 128; o; o >>= 1) {
        if (t < o) sm[t] += sm[t + o];
        __syncthreads();
    }
    if (t == 0) out[0] = sm[0] / (float)BROWS;
}

// ---------------------------------------------------------------------------
extern "C" void kernel_launch(void* const* d_in, const int* in_sizes, int n_in,
                              void* d_out, int out_size) {
    const float* feat   = (const float*)d_in[0];
    const int*   ids    = (const int*)d_in[1];
    const int*   anchor = (const int*)d_in[2];
    float*       out    = (float*)d_out;

    dim3 b32x8(32, 8);
    normalize_kernel<<<BROWS / 8, b32x8>>>(feat);

    dim3 grid(BROWS / TM, JSPLIT);
    gemm_lse_kernel<<<grid, 256>>>();

    pick_kernel<<<BROWS / 8, b32x8>>>(ids, anchor);
    finalize_kernel<<<1, 256>>>(out);
}

// round 3
// speedup vs baseline: 2.8946x; 2.8946x over previous
#include <cuda_runtime.h>
#include <cstdint>
#include <math.h>

// Problem constants
#define BROWS 8192
#define DIM   512
#define INV_T 14.285714285714286f   // 1/0.07

// Tiling: CTA 128x128, warp 32x64, mma m16n8k8 tf32
#define TM 128
#define TN 128
#define KC 32
#define NCHUNK (DIM / KC)           // 16
#define RB (BROWS / TM)             // 64
#define JB (BROWS / TN)             // 64

#define STAGE_FLOATS 8192           // A 4096 + B 4096 (32 KB)
#define SMEM_BYTES   (2 * STAGE_FLOATS * 4)   // 64 KB double buffered

// Scratch (static device globals — no allocation)
__device__ float g_f[BROWS * DIM];        // tf32-rounded normalized features
__device__ float g_partial[JB][BROWS];    // per-jblock exp row sums
__device__ float g_rowval[BROWS];

// ---------------------------------------------------------------------------
__device__ __forceinline__ void mma_tf32(float* c, const uint4& a, const uint2& b) {
    asm volatile(
        "mma.sync.aligned.m16n8k8.row.col.f32.tf32.tf32.f32 "
        "{%0,%1,%2,%3}, {%4,%5,%6,%7}, {%8,%9}, {%0,%1,%2,%3};"
        : "+f"(c[0]), "+f"(c[1]), "+f"(c[2]), "+f"(c[3])
        : "r"(a.x), "r"(a.y), "r"(a.z), "r"(a.w), "r"(b.x), "r"(b.y));
}

// ---------------------------------------------------------------------------
// Kernel A: row L2-normalize + round to tf32 grid
// ---------------------------------------------------------------------------
__global__ void normalize_kernel(const float* __restrict__ x) {
    int row  = blockIdx.x * 8 + threadIdx.y;
    int lane = threadIdx.x;
    const float* xr = x + (size_t)row * DIM;
    float v[16];
    float s = 0.f;
#pragma unroll
    for (int i = 0; i < 16; i++) { v[i] = xr[lane + i * 32]; s += v[i] * v[i]; }
#pragma unroll
    for (int o = 16; o; o >>= 1) s += __shfl_xor_sync(0xffffffffu, s, o);
    float inv = 1.0f / fmaxf(sqrtf(s), 1e-12f);
    float* fr = g_f + (size_t)row * DIM;
#pragma unroll
    for (int i = 0; i < 16; i++) {
        float y = v[i] * inv;
        uint32_t u;
        asm("cvt.rna.tf32.f32 %0, %1;" : "=r"(u) : "f"(y));
        fr[lane + i * 32] = __uint_as_float(u);
    }
}

// ---------------------------------------------------------------------------
// Kernel B: tf32 mma.sync GEMM 128x128x512 + fused exp row-sum (LSE body).
// Fragments pre-permuted into SMEM at staging (XOR-swizzled by kstep):
//   A frag slot: sA[(kstep*8 + m8)*128 + ((g*4+t)^kstep)*4 + (hi + 2*sec)]
//   B frag slot: sB[(kstep*16 + nt)*64 + ((g*4+t)^kstep)*2 + half]
// Compute loop: LDS.128 per A frag, LDS.64 per B frag — conflict-free.
// ---------------------------------------------------------------------------
extern __shared__ float dynsm[];

__global__ __launch_bounds__(256, 1) void gemm_lse_mma() {
    __shared__ float red[TM][2];

    const int tid  = threadIdx.x;
    const int wid  = tid >> 5;
    const int lane = tid & 31;
    const int wr   = wid & 3;        // warp row (M chunks of 32)
    const int wc   = wid >> 2;       // warp col (N chunks of 64)
    const int g    = lane >> 2;
    const int t    = lane & 3;
    const int r0   = blockIdx.x * TM;
    const int j0   = blockIdx.y * TN;

    const float* srcA = g_f + (size_t)r0 * DIM;
    const float* srcB = g_f + (size_t)j0 * DIM;

    float acc[2][8][4];
#pragma unroll
    for (int mt = 0; mt < 2; mt++)
#pragma unroll
        for (int nt = 0; nt < 8; nt++)
#pragma unroll
            for (int rr = 0; rr < 4; rr++) acc[mt][nt][rr] = 0.f;

    // prologue: load chunk 0 into registers
    float4 pa[4], pb[4];
#pragma unroll
    for (int it = 0; it < 4; it++) {
        int i = tid + it * 256, row = i >> 3, seg = i & 7;
        pa[it] = *(const float4*)(srcA + (size_t)row * DIM + seg * 4);
        pb[it] = *(const float4*)(srcB + (size_t)row * DIM + seg * 4);
    }

    for (int c = 0; c < NCHUNK; c++) {
        float* sA = dynsm + (c & 1) * STAGE_FLOATS;
        float* sB = sA + 4096;

        // ---- commit staged registers into fragment-order SMEM ----
#pragma unroll
        for (int it = 0; it < 4; it++) {
            int i = tid + it * 256, row = i >> 3, seg = i & 7;
            int kstep = seg >> 1, sec = seg & 1;
            // A
            {
                int m8 = row >> 4, ga = row & 7, hi = (row >> 3) & 1;
                float* ba = sA + (kstep * 8 + m8) * 128;
                int reg = hi + 2 * sec;
                ba[((ga * 4 + 0) ^ kstep) * 4 + reg] = pa[it].x;
                ba[((ga * 4 + 1) ^ kstep) * 4 + reg] = pa[it].y;
                ba[((ga * 4 + 2) ^ kstep) * 4 + reg] = pa[it].z;
                ba[((ga * 4 + 3) ^ kstep) * 4 + reg] = pa[it].w;
            }
            // B
            {
                int nt = row >> 3, gb = row & 7;
                float* bb = sB + (kstep * 16 + nt) * 64;
                bb[((gb * 4 + 0) ^ kstep) * 2 + sec] = pb[it].x;
                bb[((gb * 4 + 1) ^ kstep) * 2 + sec] = pb[it].y;
                bb[((gb * 4 + 2) ^ kstep) * 2 + sec] = pb[it].z;
                bb[((gb * 4 + 3) ^ kstep) * 2 + sec] = pb[it].w;
            }
        }

        // prefetch next chunk (hidden under compute)
        if (c + 1 < NCHUNK) {
            const int ko = (c + 1) * KC;
#pragma unroll
            for (int it = 0; it < 4; it++) {
                int i = tid + it * 256, row = i >> 3, seg = i & 7;
                pa[it] = *(const float4*)(srcA + (size_t)row * DIM + ko + seg * 4);
                pb[it] = *(const float4*)(srcB + (size_t)row * DIM + ko + seg * 4);
            }
        }
        __syncthreads();

        // ---- compute: 4 ksteps x (2 mtiles x 8 ntiles) mmas ----
#pragma unroll
        for (int kstep = 0; kstep < 4; kstep++) {
            const int le = lane ^ kstep;
            uint4 afr[2];
            afr[0] = *(const uint4*)(sA + (kstep * 8 + wr * 2 + 0) * 128 + le * 4);
            afr[1] = *(const uint4*)(sA + (kstep * 8 + wr * 2 + 1) * 128 + le * 4);
            uint2 bfr[8];
#pragma unroll
            for (int nt = 0; nt < 8; nt++)
                bfr[nt] = *(const uint2*)(sB + (kstep * 16 + wc * 8 + nt) * 64 + le * 2);
#pragma unroll
            for (int mt = 0; mt < 2; mt++)
#pragma unroll
                for (int nt = 0; nt < 8; nt++)
                    mma_tf32(acc[mt][nt], afr[mt], bfr[nt]);
        }
        __syncthreads();
    }

    // ---- epilogue: exp row-sums; diagonal shift is the constant 1 ----
#pragma unroll
    for (int mt = 0; mt < 2; mt++)
#pragma unroll
        for (int hi = 0; hi < 2; hi++) {
            float s = 0.f;
#pragma unroll
            for (int nt = 0; nt < 8; nt++) {
                s += __expf((acc[mt][nt][hi * 2 + 0] - 1.0f) * INV_T);
                s += __expf((acc[mt][nt][hi * 2 + 1] - 1.0f) * INV_T);
            }
            s += __shfl_xor_sync(0xffffffffu, s, 1);
            s += __shfl_xor_sync(0xffffffffu, s, 2);
            if (t == 0) red[wr * 32 + mt * 16 + hi * 8 + g][wc] = s;
        }
    __syncthreads();
    if (tid < TM)
        g_partial[blockIdx.y][r0 + tid] = red[tid][0] + red[tid][1];
}

// ---------------------------------------------------------------------------
// Kernel C: labels (col 0/1), picked dot, lse, per-row value
// ---------------------------------------------------------------------------
__global__ void pick_kernel(const int* __restrict__ ids,
                            const int* __restrict__ anchor) {
    int row  = blockIdx.x * 8 + threadIdx.y;
    int lane = threadIdx.x;

    int aid       = ids[anchor[0]];
    int same_last = (ids[BROWS - 1] == aid);
    int label;
    if (row == BROWS - 1)
        label = (same_last && (ids[BROWS - 2] == aid)) ? 1 : 0;
    else
        label = ((ids[row] == aid) && same_last) ? 1 : 0;

    const float* fi = g_f + (size_t)row * DIM;
    const float* fc = g_f + (size_t)label * DIM;
    float d = 0.f;
#pragma unroll
    for (int i = 0; i < 16; i++)
        d = fmaf(fi[lane + i * 32], fc[lane + i * 32], d);
#pragma unroll
    for (int o = 16; o; o >>= 1) d += __shfl_xor_sync(0xffffffffu, d, o);

    if (lane == 0) {
        float rs = 0.f;
#pragma unroll
        for (int p = 0; p < JB; p++) rs += g_partial[p][row];
        float lse = INV_T + logf(rs);
        g_rowval[row] = lse - d * INV_T;
    }
}

// ---------------------------------------------------------------------------
// Kernel D: deterministic final reduction
// ---------------------------------------------------------------------------
__global__ void finalize_kernel(float* __restrict__ out) {
    __shared__ float sm[256];
    int tdx = threadIdx.x;
    float s = 0.f;
    for (int i = tdx; i < BROWS; i += 256) s += g_rowval[i];
    sm[tdx] = s;
    __syncthreads();
#pragma unroll
    for (int o = 128; o; o >>= 1) {
        if (tdx < o) sm[tdx] += sm[tdx + o];
        __syncthreads();
    }
    if (tdx == 0) out[0] = sm[0] / (float)BROWS;
}

// ---------------------------------------------------------------------------
extern "C" void kernel_launch(void* const* d_in, const int* in_sizes, int n_in,
                              void* d_out, int out_size) {
    const float* feat   = (const float*)d_in[0];
    const int*   ids    = (const int*)d_in[1];
    const int*   anchor = (const int*)d_in[2];
    float*       out    = (float*)d_out;

    cudaFuncSetAttribute(gemm_lse_mma,
                         cudaFuncAttributeMaxDynamicSharedMemorySize, SMEM_BYTES);

    dim3 b32x8(32, 8);
    normalize_kernel<<<BROWS / 8, b32x8>>>(feat);

    dim3 grid(RB, JB);
    gemm_lse_mma<<<grid, 256, SMEM_BYTES>>>();

    pick_kernel<<<BROWS / 8, b32x8>>>(ids, anchor);
    finalize_kernel<<<1, 256>>>(out);
}

// round 4
// speedup vs baseline: 5.4803x; 1.8933x over previous
#include <cuda_runtime.h>
#include <cuda_bf16.h>
#include <cstdint>
#include <math.h>

// Problem constants
#define BROWS 8192
#define DIM   512
#define INV_T 14.285714285714286f   // 1/0.07

// Tiling: CTA 128x128, warp 32x64, mma m16n8k16 bf16
#define TM 128
#define TN 128
#define KC 64                        // bf16 elements per chunk (128B rows)
#define NCHUNK (DIM / KC)            // 8
#define RB (BROWS / TM)              // 64
#define JB (BROWS / TN)              // 64

#define TILE_BYTES  (128 * 128)      // one 128-row x 128B tile (16 KB)
#define STAGE_BYTES (2 * TILE_BYTES) // A + B (32 KB)
#define SMEM_BYTES  (2 * STAGE_BYTES)// double buffered (64 KB)

#define SWZ(o) ((o) ^ (((o) >> 3) & 0x70))

// Scratch (static device globals — no allocation)
__device__ __nv_bfloat16 g_f[BROWS * DIM];   // bf16 normalized features (8 MB)
__device__ float g_partial[JB][BROWS];       // per-jblock exp row sums
__device__ float g_rowval[BROWS];

// ---------------------------------------------------------------------------
__device__ __forceinline__ uint32_t smem_u32(const void* p) {
    uint32_t a;
    asm("{ .reg .u64 t; cvta.to.shared.u64 t, %1; cvt.u32.u64 %0, t; }"
        : "=r"(a) : "l"(p));
    return a;
}
__device__ __forceinline__ void ldsm_x4(uint32_t* r, uint32_t addr) {
    asm volatile("ldmatrix.sync.aligned.m8n8.x4.shared.b16 {%0,%1,%2,%3}, [%4];"
                 : "=r"(r[0]), "=r"(r[1]), "=r"(r[2]), "=r"(r[3]) : "r"(addr));
}
__device__ __forceinline__ void mma_bf16(float* c, const uint32_t* a,
                                         uint32_t b0, uint32_t b1) {
    asm volatile(
        "mma.sync.aligned.m16n8k16.row.col.f32.bf16.bf16.f32 "
        "{%0,%1,%2,%3}, {%4,%5,%6,%7}, {%8,%9}, {%0,%1,%2,%3};"
        : "+f"(c[0]), "+f"(c[1]), "+f"(c[2]), "+f"(c[3])
        : "r"(a[0]), "r"(a[1]), "r"(a[2]), "r"(a[3]), "r"(b0), "r"(b1));
}

// ---------------------------------------------------------------------------
// Kernel A: row L2-normalize + round to bf16
// ---------------------------------------------------------------------------
__global__ void normalize_kernel(const float* __restrict__ x) {
    int row  = blockIdx.x * 8 + threadIdx.y;
    int lane = threadIdx.x;
    const float* xr = x + (size_t)row * DIM;
    float v[16];
    float s = 0.f;
#pragma unroll
    for (int i = 0; i < 16; i++) { v[i] = xr[lane + i * 32]; s += v[i] * v[i]; }
#pragma unroll
    for (int o = 16; o; o >>= 1) s += __shfl_xor_sync(0xffffffffu, s, o);
    float inv = 1.0f / fmaxf(sqrtf(s), 1e-12f);
    __nv_bfloat16* fr = g_f + (size_t)row * DIM;
#pragma unroll
    for (int i = 0; i < 16; i++)
        fr[lane + i * 32] = __float2bfloat16_rn(v[i] * inv);
}

// ---------------------------------------------------------------------------
// Kernel B: bf16 mma.sync GEMM 128x128x512 + fused exp row-sum (LSE body).
// Tiles stored row-major (128B rows) with SW128 XOR swizzle; fragments via
// ldmatrix.x4. Double-buffered SMEM, register prefetch of next chunk.
// ---------------------------------------------------------------------------
extern __shared__ char dynsm[];

__global__ __launch_bounds__(256, 1) void gemm_lse_mma() {
    __shared__ float red[TM][2];

    const int tid  = threadIdx.x;
    const int wid  = tid >> 5;
    const int lane = tid & 31;
    const int wr   = wid & 3;        // warp row (M chunks of 32)
    const int wc   = wid >> 2;       // warp col (N chunks of 64)
    const int g    = lane >> 2;
    const int t    = lane & 3;
    const int r0   = blockIdx.x * TM;
    const int j0   = blockIdx.y * TN;

    const __nv_bfloat16* srcA = g_f + (size_t)r0 * DIM;
    const __nv_bfloat16* srcB = g_f + (size_t)j0 * DIM;

    const uint32_t smem_base = smem_u32(dynsm);

    // staging mapping: i -> (row, seg); each thread stores 16B
    const int srow = tid >> 3;       // step 32 rows per iter
    const int sseg = tid & 7;

    // ldmatrix per-lane offsets (byte offsets within a tile, pre-swizzle parts)
    // A: row = wr*32 + mt*16 + (lane&15), kbyte = (lane>>4)*16 (+32 per kstep)
    const int a_row  = wr * 32 + (lane & 15);
    const int a_koff = (lane >> 4) * 16;
    // B: nrow = wc*64 + p*16 + (lane&7) + (lane>>4)*8, kbyte = ((lane>>3)&1)*16
    const int b_row  = wc * 64 + (lane & 7) + ((lane >> 4) << 3);
    const int b_koff = ((lane >> 3) & 1) * 16;

    float acc[2][8][4];
#pragma unroll
    for (int mt = 0; mt < 2; mt++)
#pragma unroll
        for (int nt = 0; nt < 8; nt++)
#pragma unroll
            for (int rr = 0; rr < 4; rr++) acc[mt][nt][rr] = 0.f;

    // prologue: load chunk 0 into registers (4 x float4 per matrix)
    float4 pa[4], pb[4];
#pragma unroll
    for (int it = 0; it < 4; it++) {
        int row = srow + it * 32;
        pa[it] = *(const float4*)(srcA + (size_t)row * DIM + sseg * 8);
        pb[it] = *(const float4*)(srcB + (size_t)row * DIM + sseg * 8);
    }

    for (int c = 0; c < NCHUNK; c++) {
        char* stage = dynsm + (c & 1) * STAGE_BYTES;
        const uint32_t sa = smem_base + (c & 1) * STAGE_BYTES;
        const uint32_t sb = sa + TILE_BYTES;

        // ---- commit staged registers into swizzled SMEM tiles ----
#pragma unroll
        for (int it = 0; it < 4; it++) {
            int row = srow + it * 32;
            int off = SWZ(row * 128 + sseg * 16);
            *(float4*)(stage + off) = pa[it];
            *(float4*)(stage + TILE_BYTES + off) = pb[it];
        }

        // prefetch next chunk
        if (c + 1 < NCHUNK) {
            const int ko = (c + 1) * KC;
#pragma unroll
            for (int it = 0; it < 4; it++) {
                int row = srow + it * 32;
                pa[it] = *(const float4*)(srcA + (size_t)row * DIM + ko + sseg * 8);
                pb[it] = *(const float4*)(srcB + (size_t)row * DIM + ko + sseg * 8);
            }
        }
        __syncthreads();

        // ---- compute: 4 ksteps (k16 each) x 2 mtiles x 8 ntiles ----
#pragma unroll
        for (int kstep = 0; kstep < 4; kstep++) {
            uint32_t afr[2][4];
#pragma unroll
            for (int mt = 0; mt < 2; mt++) {
                int off = SWZ((a_row + mt * 16) * 128 + kstep * 32 + a_koff);
                ldsm_x4(afr[mt], sa + off);
            }
            uint32_t bfr[8][2];
#pragma unroll
            for (int p = 0; p < 4; p++) {
                uint32_t r[4];
                int off = SWZ((b_row + p * 16) * 128 + kstep * 32 + b_koff);
                ldsm_x4(r, sb + off);
                bfr[2 * p][0] = r[0]; bfr[2 * p][1] = r[1];
                bfr[2 * p + 1][0] = r[2]; bfr[2 * p + 1][1] = r[3];
            }
#pragma unroll
            for (int mt = 0; mt < 2; mt++)
#pragma unroll
                for (int nt = 0; nt < 8; nt++)
                    mma_bf16(acc[mt][nt], afr[mt], bfr[nt][0], bfr[nt][1]);
        }
        __syncthreads();
    }

    // ---- epilogue: exp row-sums; diagonal shift is the constant 1 ----
#pragma unroll
    for (int mt = 0; mt < 2; mt++)
#pragma unroll
        for (int hi = 0; hi < 2; hi++) {
            float s = 0.f;
#pragma unroll
            for (int nt = 0; nt < 8; nt++) {
                s += __expf((acc[mt][nt][hi * 2 + 0] - 1.0f) * INV_T);
                s += __expf((acc[mt][nt][hi * 2 + 1] - 1.0f) * INV_T);
            }
            s += __shfl_xor_sync(0xffffffffu, s, 1);
            s += __shfl_xor_sync(0xffffffffu, s, 2);
            if (t == 0) red[wr * 32 + mt * 16 + hi * 8 + g][wc] = s;
        }
    __syncthreads();
    if (tid < TM)
        g_partial[blockIdx.y][r0 + tid] = red[tid][0] + red[tid][1];
}

// ---------------------------------------------------------------------------
// Kernel C: labels (col 0/1), picked dot (bf16 inputs, fp32 accum), lse
// ---------------------------------------------------------------------------
__global__ void pick_kernel(const int* __restrict__ ids,
                            const int* __restrict__ anchor) {
    int row  = blockIdx.x * 8 + threadIdx.y;
    int lane = threadIdx.x;

    int aid       = ids[anchor[0]];
    int same_last = (ids[BROWS - 1] == aid);
    int label;
    if (row == BROWS - 1)
        label = (same_last && (ids[BROWS - 2] == aid)) ? 1 : 0;
    else
        label = ((ids[row] == aid) && same_last) ? 1 : 0;

    const __nv_bfloat16* fi = g_f + (size_t)row * DIM;
    const __nv_bfloat16* fc = g_f + (size_t)label * DIM;
    float d = 0.f;
#pragma unroll
    for (int i = 0; i < 16; i++)
        d = fmaf(__bfloat162float(fi[lane + i * 32]),
                 __bfloat162float(fc[lane + i * 32]), d);
#pragma unroll
    for (int o = 16; o; o >>= 1) d += __shfl_xor_sync(0xffffffffu, d, o);

    if (lane == 0) {
        float rs = 0.f;
#pragma unroll
        for (int p = 0; p < JB; p++) rs += g_partial[p][row];
        float lse = INV_T + logf(rs);
        g_rowval[row] = lse - d * INV_T;
    }
}

// ---------------------------------------------------------------------------
// Kernel D: deterministic final reduction
// ---------------------------------------------------------------------------
__global__ void finalize_kernel(float* __restrict__ out) {
    __shared__ float sm[256];
    int tdx = threadIdx.x;
    float s = 0.f;
    for (int i = tdx; i < BROWS; i += 256) s += g_rowval[i];
    sm[tdx] = s;
    __syncthreads();
#pragma unroll
    for (int o = 128; o; o >>= 1) {
        if (tdx < o) sm[tdx] += sm[tdx + o];
        __syncthreads();
    }
    if (tdx == 0) out[0] = sm[0] / (float)BROWS;
}

// ---------------------------------------------------------------------------
extern "C" void kernel_launch(void* const* d_in, const int* in_sizes, int n_in,
                              void* d_out, int out_size) {
    const float* feat   = (const float*)d_in[0];
    const int*   ids    = (const int*)d_in[1];
    const int*   anchor = (const int*)d_in[2];
    float*       out    = (float*)d_out;

    cudaFuncSetAttribute(gemm_lse_mma,
                         cudaFuncAttributeMaxDynamicSharedMemorySize, SMEM_BYTES);

    dim3 b32x8(32, 8);
    normalize_kernel<<<BROWS / 8, b32x8>>>(feat);

    dim3 grid(RB, JB);
    gemm_lse_mma<<<grid, 256, SMEM_BYTES>>>();

    pick_kernel<<<BROWS / 8, b32x8>>>(ids, anchor);
    finalize_kernel<<<1, 256>>>(out);
}

// round 5
// speedup vs baseline: 9.8116x; 1.7903x over previous
#include <cuda_runtime.h>
#include <cuda_bf16.h>
#include <cstdint>
#include <math.h>

// Problem constants
#define BROWS 8192
#define DIM   512
#define INV_T 14.285714285714286f   // 1/0.07

// Tiling: CTA 128x128, warp 32x64, mma m16n8k16 bf16
#define TM 128
#define TN 128
#define KC 64                        // bf16 elements per chunk (128B rows)
#define NCHUNK (DIM / KC)            // 8
#define NB (BROWS / TM)              // 64 blocks per dim
#define NTILES (NB * (NB + 1) / 2)   // 2080 lower-tri tiles

#define TILE_BYTES  (128 * 128)      // one 128-row x 128B tile (16 KB)
#define STAGE_BYTES (2 * TILE_BYTES) // A + B (32 KB)
#define SMEM_BYTES  (2 * STAGE_BYTES)// double buffered (64 KB)

#define SWZ(o) ((o) ^ (((o) >> 3) & 0x70))

// Scratch (static device globals — no allocation)
__device__ __nv_bfloat16 g_f[BROWS * DIM];   // bf16 normalized features (8 MB)
__device__ float g_partial[NB][BROWS];       // per-block exp row sums
__device__ float g_rowval[BROWS];

// ---------------------------------------------------------------------------
__device__ __forceinline__ uint32_t smem_u32(const void* p) {
    uint32_t a;
    asm("{ .reg .u64 t; cvta.to.shared.u64 t, %1; cvt.u32.u64 %0, t; }"
        : "=r"(a) : "l"(p));
    return a;
}
__device__ __forceinline__ void ldsm_x4(uint32_t* r, uint32_t addr) {
    asm volatile("ldmatrix.sync.aligned.m8n8.x4.shared.b16 {%0,%1,%2,%3}, [%4];"
                 : "=r"(r[0]), "=r"(r[1]), "=r"(r[2]), "=r"(r[3]) : "r"(addr));
}
__device__ __forceinline__ void mma_bf16(float* c, const uint32_t* a,
                                         uint32_t b0, uint32_t b1) {
    asm volatile(
        "mma.sync.aligned.m16n8k16.row.col.f32.bf16.bf16.f32 "
        "{%0,%1,%2,%3}, {%4,%5,%6,%7}, {%8,%9}, {%0,%1,%2,%3};"
        : "+f"(c[0]), "+f"(c[1]), "+f"(c[2]), "+f"(c[3])
        : "r"(a[0]), "r"(a[1]), "r"(a[2]), "r"(a[3]), "r"(b0), "r"(b1));
}

// ---------------------------------------------------------------------------
// Kernel A: row L2-normalize + round to bf16
// ---------------------------------------------------------------------------
__global__ void normalize_kernel(const float* __restrict__ x) {
    int row  = blockIdx.x * 8 + threadIdx.y;
    int lane = threadIdx.x;
    const float* xr = x + (size_t)row * DIM;
    float v[16];
    float s = 0.f;
#pragma unroll
    for (int i = 0; i < 16; i++) { v[i] = xr[lane + i * 32]; s += v[i] * v[i]; }
#pragma unroll
    for (int o = 16; o; o >>= 1) s += __shfl_xor_sync(0xffffffffu, s, o);
    float inv = 1.0f / fmaxf(sqrtf(s), 1e-12f);
    __nv_bfloat16* fr = g_f + (size_t)row * DIM;
#pragma unroll
    for (int i = 0; i < 16; i++)
        fr[lane + i * 32] = __float2bfloat16_rn(v[i] * inv);
}

// ---------------------------------------------------------------------------
// Kernel B: bf16 mma.sync GEMM on the LOWER-TRIANGULAR tile set only.
// exp tile is symmetric across the full matrix, so an off-diagonal tile
// (bi,bj) provides row sums for block bi AND column sums (= row sums of the
// mirrored tile) for block bj. Each g_partial slot written by exactly one CTA.
// ---------------------------------------------------------------------------
extern __shared__ char dynsm[];

__global__ __launch_bounds__(256, 1) void gemm_lse_mma() {
    __shared__ float red_r[TM][2];
    __shared__ float red_c[TN][4];

    const int tid  = threadIdx.x;
    const int wid  = tid >> 5;
    const int lane = tid & 31;
    const int wr   = wid & 3;        // warp row (M chunks of 32)
    const int wc   = wid >> 2;       // warp col (N chunks of 64)
    const int g    = lane >> 2;
    const int t    = lane & 3;

    // decode lower-tri pair (bi >= bj) from 1D block index
    int idx = blockIdx.x;
    int bi = (int)((sqrtf(8.0f * (float)idx + 1.0f) - 1.0f) * 0.5f);
    while ((bi + 1) * (bi + 2) / 2 <= idx) bi++;
    while (bi * (bi + 1) / 2 > idx) bi--;
    int bj = idx - bi * (bi + 1) / 2;
    const int r0 = bi * TM;
    const int j0 = bj * TN;
    const bool offdiag = (bi != bj);

    const __nv_bfloat16* srcA = g_f + (size_t)r0 * DIM;
    const __nv_bfloat16* srcB = g_f + (size_t)j0 * DIM;

    const uint32_t smem_base = smem_u32(dynsm);

    const int srow = tid >> 3;
    const int sseg = tid & 7;

    const int a_row  = wr * 32 + (lane & 15);
    const int a_koff = (lane >> 4) * 16;
    const int b_row  = wc * 64 + (lane & 7) + ((lane >> 4) << 3);
    const int b_koff = ((lane >> 3) & 1) * 16;

    float acc[2][8][4];
#pragma unroll
    for (int mt = 0; mt < 2; mt++)
#pragma unroll
        for (int nt = 0; nt < 8; nt++)
#pragma unroll
            for (int rr = 0; rr < 4; rr++) acc[mt][nt][rr] = 0.f;

    // prologue: load chunk 0
    float4 pa[4], pb[4];
#pragma unroll
    for (int it = 0; it < 4; it++) {
        int row = srow + it * 32;
        pa[it] = *(const float4*)(srcA + (size_t)row * DIM + sseg * 8);
        pb[it] = *(const float4*)(srcB + (size_t)row * DIM + sseg * 8);
    }

    for (int c = 0; c < NCHUNK; c++) {
        char* stage = dynsm + (c & 1) * STAGE_BYTES;
        const uint32_t sa = smem_base + (c & 1) * STAGE_BYTES;
        const uint32_t sb = sa + TILE_BYTES;

#pragma unroll
        for (int it = 0; it < 4; it++) {
            int row = srow + it * 32;
            int off = SWZ(row * 128 + sseg * 16);
            *(float4*)(stage + off) = pa[it];
            *(float4*)(stage + TILE_BYTES + off) = pb[it];
        }

        if (c + 1 < NCHUNK) {
            const int ko = (c + 1) * KC;
#pragma unroll
            for (int it = 0; it < 4; it++) {
                int row = srow + it * 32;
                pa[it] = *(const float4*)(srcA + (size_t)row * DIM + ko + sseg * 8);
                pb[it] = *(const float4*)(srcB + (size_t)row * DIM + ko + sseg * 8);
            }
        }
        __syncthreads();

#pragma unroll
        for (int kstep = 0; kstep < 4; kstep++) {
            uint32_t afr[2][4];
#pragma unroll
            for (int mt = 0; mt < 2; mt++) {
                int off = SWZ((a_row + mt * 16) * 128 + kstep * 32 + a_koff);
                ldsm_x4(afr[mt], sa + off);
            }
            uint32_t bfr[8][2];
#pragma unroll
            for (int p = 0; p < 4; p++) {
                uint32_t r[4];
                int off = SWZ((b_row + p * 16) * 128 + kstep * 32 + b_koff);
                ldsm_x4(r, sb + off);
                bfr[2 * p][0] = r[0]; bfr[2 * p][1] = r[1];
                bfr[2 * p + 1][0] = r[2]; bfr[2 * p + 1][1] = r[3];
            }
#pragma unroll
            for (int mt = 0; mt < 2; mt++)
#pragma unroll
                for (int nt = 0; nt < 8; nt++)
                    mma_bf16(acc[mt][nt], afr[mt], bfr[nt][0], bfr[nt][1]);
        }
        __syncthreads();
    }

    // ---- epilogue: exp in place, then row sums (+ col sums if off-diag) ----
#pragma unroll
    for (int mt = 0; mt < 2; mt++)
#pragma unroll
        for (int nt = 0; nt < 8; nt++)
#pragma unroll
            for (int rr = 0; rr < 4; rr++)
                acc[mt][nt][rr] = __expf((acc[mt][nt][rr] - 1.0f) * INV_T);

    // row sums: acc row = wr*32 + mt*16 + hi*8 + g, reduce over t
#pragma unroll
    for (int mt = 0; mt < 2; mt++)
#pragma unroll
        for (int hi = 0; hi < 2; hi++) {
            float s = 0.f;
#pragma unroll
            for (int nt = 0; nt < 8; nt++)
                s += acc[mt][nt][hi * 2 + 0] + acc[mt][nt][hi * 2 + 1];
            s += __shfl_xor_sync(0xffffffffu, s, 1);
            s += __shfl_xor_sync(0xffffffffu, s, 2);
            if (t == 0) red_r[wr * 32 + mt * 16 + hi * 8 + g][wc] = s;
        }

    // col sums: col = wc*64 + nt*8 + t*2 + {0,1}; reduce over g (lanes ^4,^8,^16)
    if (offdiag) {
#pragma unroll
        for (int nt = 0; nt < 8; nt++) {
            float cs0 = acc[0][nt][0] + acc[0][nt][2] + acc[1][nt][0] + acc[1][nt][2];
            float cs1 = acc[0][nt][1] + acc[0][nt][3] + acc[1][nt][1] + acc[1][nt][3];
#pragma unroll
            for (int o = 4; o <= 16; o <<= 1) {
                cs0 += __shfl_xor_sync(0xffffffffu, cs0, o);
                cs1 += __shfl_xor_sync(0xffffffffu, cs1, o);
            }
            if (g == 0) {
                red_c[wc * 64 + nt * 8 + t * 2 + 0][wr] = cs0;
                red_c[wc * 64 + nt * 8 + t * 2 + 1][wr] = cs1;
            }
        }
    }
    __syncthreads();

    if (tid < TM) {
        g_partial[bj][r0 + tid] = red_r[tid][0] + red_r[tid][1];
        if (offdiag)
            g_partial[bi][j0 + tid] =
                red_c[tid][0] + red_c[tid][1] + red_c[tid][2] + red_c[tid][3];
    }
}

// ---------------------------------------------------------------------------
// Kernel C: labels (col 0/1), picked dot (bf16 inputs, fp32 accum), lse
// ---------------------------------------------------------------------------
__global__ void pick_kernel(const int* __restrict__ ids,
                            const int* __restrict__ anchor) {
    int row  = blockIdx.x * 8 + threadIdx.y;
    int lane = threadIdx.x;

    int aid       = ids[anchor[0]];
    int same_last = (ids[BROWS - 1] == aid);
    int label;
    if (row == BROWS - 1)
        label = (same_last && (ids[BROWS - 2] == aid)) ? 1 : 0;
    else
        label = ((ids[row] == aid) && same_last) ? 1 : 0;

    const __nv_bfloat16* fi = g_f + (size_t)row * DIM;
    const __nv_bfloat16* fc = g_f + (size_t)label * DIM;
    float d = 0.f;
#pragma unroll
    for (int i = 0; i < 16; i++)
        d = fmaf(__bfloat162float(fi[lane + i * 32]),
                 __bfloat162float(fc[lane + i * 32]), d);
#pragma unroll
    for (int o = 16; o; o >>= 1) d += __shfl_xor_sync(0xffffffffu, d, o);

    if (lane == 0) {
        float rs = 0.f;
#pragma unroll
        for (int p = 0; p < NB; p++) rs += g_partial[p][row];
        float lse = INV_T + logf(rs);
        g_rowval[row] = lse - d * INV_T;
    }
}

// ---------------------------------------------------------------------------
// Kernel D: deterministic final reduction
// ---------------------------------------------------------------------------
__global__ void finalize_kernel(float* __restrict__ out) {
    __shared__ float sm[256];
    int tdx = threadIdx.x;
    float s = 0.f;
    for (int i = tdx; i < BROWS; i += 256) s += g_rowval[i];
    sm[tdx] = s;
    __syncthreads();
#pragma unroll
    for (int o = 128; o; o >>= 1) {
        if (tdx < o) sm[tdx] += sm[tdx + o];
        __syncthreads();
    }
    if (tdx == 0) out[0] = sm[0] / (float)BROWS;
}

// ---------------------------------------------------------------------------
extern "C" void kernel_launch(void* const* d_in, const int* in_sizes, int n_in,
                              void* d_out, int out_size) {
    const float* feat   = (const float*)d_in[0];
    const int*   ids    = (const int*)d_in[1];
    const int*   anchor = (const int*)d_in[2];
    float*       out    = (float*)d_out;

    cudaFuncSetAttribute(gemm_lse_mma,
                         cudaFuncAttributeMaxDynamicSharedMemorySize, SMEM_BYTES);

    dim3 b32x8(32, 8);
    normalize_kernel<<<BROWS / 8, b32x8>>>(feat);

    gemm_lse_mma<<<NTILES, 256, SMEM_BYTES>>>();

    pick_kernel<<<BROWS / 8, b32x8>>>(ids, anchor);
    finalize_kernel<<<1, 256>>>(out);
}

// round 6
// speedup vs baseline: 14.1518x; 1.4423x over previous
#include <cuda_runtime.h>
#include <cuda_bf16.h>
#include <cstdint>
#include <math.h>

// Problem constants
#define BROWS 8192
#define DIM   512
#define INV_T 14.285714285714286f   // 1/0.07

// Tiling: CTA 128x128, warp 32x64, mma m16n8k16 bf16
#define TM 128
#define TN 128
#define KC 64                        // bf16 elements per chunk (128B rows)
#define NCHUNK (DIM / KC)            // 8
#define NB (BROWS / TM)              // 64 blocks per dim
#define NTILES (NB * (NB + 1) / 2)   // 2080 lower-tri tiles

#define TILE_BYTES  (128 * 128)      // one 128-row x 128B tile (16 KB)
#define STAGE_BYTES (2 * TILE_BYTES) // A + B (32 KB)
#define STAGES 3
#define SMEM_BYTES  (STAGES * STAGE_BYTES)   // 96 KB

#define SWZ(o) ((o) ^ (((o) >> 3) & 0x70))

// Scratch (static device globals — no allocation)
__device__ __nv_bfloat16 g_f[BROWS * DIM];   // bf16 normalized features (8 MB)
__device__ float g_partial[NB][BROWS];       // per-block exp row sums
__device__ float g_rowval[BROWS];

// ---------------------------------------------------------------------------
__device__ __forceinline__ uint32_t smem_u32(const void* p) {
    uint32_t a;
    asm("{ .reg .u64 t; cvta.to.shared.u64 t, %1; cvt.u32.u64 %0, t; }"
        : "=r"(a) : "l"(p));
    return a;
}
__device__ __forceinline__ void cp16(uint32_t dst, const void* src) {
    asm volatile("cp.async.cg.shared.global [%0], [%1], 16;"
                 :: "r"(dst), "l"(src) : "memory");
}
__device__ __forceinline__ void ldsm_x4(uint32_t* r, uint32_t addr) {
    asm volatile("ldmatrix.sync.aligned.m8n8.x4.shared.b16 {%0,%1,%2,%3}, [%4];"
                 : "=r"(r[0]), "=r"(r[1]), "=r"(r[2]), "=r"(r[3]) : "r"(addr));
}
__device__ __forceinline__ void mma_bf16(float* c, const uint32_t* a,
                                         uint32_t b0, uint32_t b1) {
    asm volatile(
        "mma.sync.aligned.m16n8k16.row.col.f32.bf16.bf16.f32 "
        "{%0,%1,%2,%3}, {%4,%5,%6,%7}, {%8,%9}, {%0,%1,%2,%3};"
        : "+f"(c[0]), "+f"(c[1]), "+f"(c[2]), "+f"(c[3])
        : "r"(a[0]), "r"(a[1]), "r"(a[2]), "r"(a[3]), "r"(b0), "r"(b1));
}

// ---------------------------------------------------------------------------
// Kernel A: row L2-normalize + round to bf16
// ---------------------------------------------------------------------------
__global__ void normalize_kernel(const float* __restrict__ x) {
    int row  = blockIdx.x * 8 + threadIdx.y;
    int lane = threadIdx.x;
    const float* xr = x + (size_t)row * DIM;
    float v[16];
    float s = 0.f;
#pragma unroll
    for (int i = 0; i < 16; i++) { v[i] = xr[lane + i * 32]; s += v[i] * v[i]; }
#pragma unroll
    for (int o = 16; o; o >>= 1) s += __shfl_xor_sync(0xffffffffu, s, o);
    float inv = 1.0f / fmaxf(sqrtf(s), 1e-12f);
    __nv_bfloat16* fr = g_f + (size_t)row * DIM;
#pragma unroll
    for (int i = 0; i < 16; i++)
        fr[lane + i * 32] = __float2bfloat16_rn(v[i] * inv);
}

// ---------------------------------------------------------------------------
// Kernel B: bf16 mma.sync GEMM, lower-tri tiles, cp.async 3-stage pipeline.
// Off-diagonal tile (bi,bj): row sums -> g_partial[bj][rows of bi],
// col sums -> g_partial[bi][rows of bj]. Deterministic (one writer per slot).
// ---------------------------------------------------------------------------
extern __shared__ char dynsm[];

__global__ __launch_bounds__(256, 2) void gemm_lse_mma() {
    __shared__ float red_r[TM][2];
    __shared__ float red_c[TN][4];

    const int tid  = threadIdx.x;
    const int wid  = tid >> 5;
    const int lane = tid & 31;
    const int wr   = wid & 3;
    const int wc   = wid >> 2;
    const int g    = lane >> 2;
    const int t    = lane & 3;

    // decode lower-tri pair (bi >= bj)
    int idx = blockIdx.x;
    int bi = (int)((sqrtf(8.0f * (float)idx + 1.0f) - 1.0f) * 0.5f);
    while ((bi + 1) * (bi + 2) / 2 <= idx) bi++;
    while (bi * (bi + 1) / 2 > idx) bi--;
    int bj = idx - bi * (bi + 1) / 2;
    const int r0 = bi * TM;
    const int j0 = bj * TN;
    const bool offdiag = (bi != bj);

    const __nv_bfloat16* srcA = g_f + (size_t)r0 * DIM;
    const __nv_bfloat16* srcB = g_f + (size_t)j0 * DIM;

    const uint32_t smem_base = smem_u32(dynsm);

    const int srow = tid >> 3;       // base row; +32 per iter
    const int sseg = tid & 7;        // 16B segment within the 128B row

    const int a_row  = wr * 32 + (lane & 15);
    const int a_koff = (lane >> 4) * 16;
    const int b_row  = wc * 64 + (lane & 7) + ((lane >> 4) << 3);
    const int b_koff = ((lane >> 3) & 1) * 16;

    float acc[2][8][4];
#pragma unroll
    for (int mt = 0; mt < 2; mt++)
#pragma unroll
        for (int nt = 0; nt < 8; nt++)
#pragma unroll
            for (int rr = 0; rr < 4; rr++) acc[mt][nt][rr] = 0.f;

    // --- async copy of one chunk into stage buffer s ---
    auto issue_chunk = [&](int c, int s) {
        const uint32_t sa = smem_base + s * STAGE_BYTES;
        const int ko = c * KC;
#pragma unroll
        for (int it = 0; it < 4; it++) {
            int row = srow + it * 32;
            uint32_t off = SWZ(row * 128 + sseg * 16);
            cp16(sa + off, srcA + (size_t)row * DIM + ko + sseg * 8);
            cp16(sa + TILE_BYTES + off, srcB + (size_t)row * DIM + ko + sseg * 8);
        }
        asm volatile("cp.async.commit_group;" ::: "memory");
    };

    // prologue: stages 0..STAGES-2
#pragma unroll
    for (int s = 0; s < STAGES - 1; s++) issue_chunk(s, s);

    for (int c = 0; c < NCHUNK; c++) {
        if (c + STAGES - 1 < NCHUNK) {
            issue_chunk(c + STAGES - 1, (c + STAGES - 1) % STAGES);
            asm volatile("cp.async.wait_group %0;" :: "n"(STAGES - 2) : "memory");
        } else {
            asm volatile("cp.async.wait_group 0;" ::: "memory");
        }
        __syncthreads();

        const uint32_t sa = smem_base + (c % STAGES) * STAGE_BYTES;
        const uint32_t sb = sa + TILE_BYTES;

#pragma unroll
        for (int kstep = 0; kstep < 4; kstep++) {
            uint32_t afr[2][4];
#pragma unroll
            for (int mt = 0; mt < 2; mt++) {
                int off = SWZ((a_row + mt * 16) * 128 + kstep * 32 + a_koff);
                ldsm_x4(afr[mt], sa + off);
            }
            uint32_t bfr[8][2];
#pragma unroll
            for (int p = 0; p < 4; p++) {
                uint32_t r[4];
                int off = SWZ((b_row + p * 16) * 128 + kstep * 32 + b_koff);
                ldsm_x4(r, sb + off);
                bfr[2 * p][0] = r[0]; bfr[2 * p][1] = r[1];
                bfr[2 * p + 1][0] = r[2]; bfr[2 * p + 1][1] = r[3];
            }
#pragma unroll
            for (int mt = 0; mt < 2; mt++)
#pragma unroll
                for (int nt = 0; nt < 8; nt++)
                    mma_bf16(acc[mt][nt], afr[mt], bfr[nt][0], bfr[nt][1]);
        }
        __syncthreads();   // all reads of this stage done before reuse
    }

    // ---- epilogue: exp in place; row sums + col sums (off-diag) ----
#pragma unroll
    for (int mt = 0; mt < 2; mt++)
#pragma unroll
        for (int nt = 0; nt < 8; nt++)
#pragma unroll
            for (int rr = 0; rr < 4; rr++)
                acc[mt][nt][rr] = __expf((acc[mt][nt][rr] - 1.0f) * INV_T);

#pragma unroll
    for (int mt = 0; mt < 2; mt++)
#pragma unroll
        for (int hi = 0; hi < 2; hi++) {
            float s = 0.f;
#pragma unroll
            for (int nt = 0; nt < 8; nt++)
                s += acc[mt][nt][hi * 2 + 0] + acc[mt][nt][hi * 2 + 1];
            s += __shfl_xor_sync(0xffffffffu, s, 1);
            s += __shfl_xor_sync(0xffffffffu, s, 2);
            if (t == 0) red_r[wr * 32 + mt * 16 + hi * 8 + g][wc] = s;
        }

    if (offdiag) {
#pragma unroll
        for (int nt = 0; nt < 8; nt++) {
            float cs0 = acc[0][nt][0] + acc[0][nt][2] + acc[1][nt][0] + acc[1][nt][2];
            float cs1 = acc[0][nt][1] + acc[0][nt][3] + acc[1][nt][1] + acc[1][nt][3];
#pragma unroll
            for (int o = 4; o <= 16; o <<= 1) {
                cs0 += __shfl_xor_sync(0xffffffffu, cs0, o);
                cs1 += __shfl_xor_sync(0xffffffffu, cs1, o);
            }
            if (g == 0) {
                red_c[wc * 64 + nt * 8 + t * 2 + 0][wr] = cs0;
                red_c[wc * 64 + nt * 8 + t * 2 + 1][wr] = cs1;
            }
        }
    }
    __syncthreads();

    if (tid < TM) {
        g_partial[bj][r0 + tid] = red_r[tid][0] + red_r[tid][1];
        if (offdiag)
            g_partial[bi][j0 + tid] =
                red_c[tid][0] + red_c[tid][1] + red_c[tid][2] + red_c[tid][3];
    }
}

// ---------------------------------------------------------------------------
// Kernel C: labels (col 0/1), picked dot, lse, per-row value
// ---------------------------------------------------------------------------
__global__ void pick_kernel(const int* __restrict__ ids,
                            const int* __restrict__ anchor) {
    int row  = blockIdx.x * 8 + threadIdx.y;
    int lane = threadIdx.x;

    int aid       = ids[anchor[0]];
    int same_last = (ids[BROWS - 1] == aid);
    int label;
    if (row == BROWS - 1)
        label = (same_last && (ids[BROWS - 2] == aid)) ? 1 : 0;
    else
        label = ((ids[row] == aid) && same_last) ? 1 : 0;

    const __nv_bfloat16* fi = g_f + (size_t)row * DIM;
    const __nv_bfloat16* fc = g_f + (size_t)label * DIM;
    float d = 0.f;
#pragma unroll
    for (int i = 0; i < 16; i++)
        d = fmaf(__bfloat162float(fi[lane + i * 32]),
                 __bfloat162float(fc[lane + i * 32]), d);

    // parallel partial-slot sum: lanes each grab 2 of the 64 slots
    float rs = g_partial[lane][row] + g_partial[lane + 32][row];

#pragma unroll
    for (int o = 16; o; o >>= 1) {
        d  += __shfl_xor_sync(0xffffffffu, d, o);
        rs += __shfl_xor_sync(0xffffffffu, rs, o);
    }

    if (lane == 0) {
        float lse = INV_T + logf(rs);
        g_rowval[row] = lse - d * INV_T;
    }
}

// ---------------------------------------------------------------------------
// Kernel D: deterministic final reduction
// ---------------------------------------------------------------------------
__global__ void finalize_kernel(float* __restrict__ out) {
    __shared__ float sm[256];
    int tdx = threadIdx.x;
    float s = 0.f;
    for (int i = tdx; i < BROWS; i += 256) s += g_rowval[i];
    sm[tdx] = s;
    __syncthreads();
#pragma unroll
    for (int o = 128; o; o >>= 1) {
        if (tdx < o) sm[tdx] += sm[tdx + o];
        __syncthreads();
    }
    if (tdx == 0) out[0] = sm[0] / (float)BROWS;
}

// ---------------------------------------------------------------------------
extern "C" void kernel_launch(void* const* d_in, const int* in_sizes, int n_in,
                              void* d_out, int out_size) {
    const float* feat   = (const float*)d_in[0];
    const int*   ids    = (const int*)d_in[1];
    const int*   anchor = (const int*)d_in[2];
    float*       out    = (float*)d_out;

    cudaFuncSetAttribute(gemm_lse_mma,
                         cudaFuncAttributeMaxDynamicSharedMemorySize, SMEM_BYTES);

    dim3 b32x8(32, 8);
    normalize_kernel<<<BROWS / 8, b32x8>>>(feat);

    gemm_lse_mma<<<NTILES, 256, SMEM_BYTES>>>();

    pick_kernel<<<BROWS / 8, b32x8>>>(ids, anchor);
    finalize_kernel<<<1, 256>>>(out);
}